// round 12
// baseline (speedup 1.0000x reference)
#include <cuda_runtime.h>
#include <math.h>

#define LAGI 5
#define POLI 3
#define BMAX 65536
#define GPB 16
#define THREADS 128
#define FULLM 0xffffffffu

__device__ double g_c[BMAX * 9];
__device__ double g_zi[BMAX * 8];
__device__ double g_roots[BMAX * 8];
__device__ float  g_fs[BMAX * 16];

__device__ __forceinline__ double dshfl(double v, int s) {
    return __shfl_sync(FULLM, v, s, 8);
}
__device__ __forceinline__ double dred(double v) {
    v += __shfl_xor_sync(FULLM, v, 4, 8);
    v += __shfl_xor_sync(FULLM, v, 2, 8);
    v += __shfl_xor_sync(FULLM, v, 1, 8);
    return v;
}
__device__ __forceinline__ float fshfl(float v, int s) {
    return __shfl_sync(FULLM, v, s, 8);
}
__device__ __forceinline__ float fred(float v) {
    v += __shfl_xor_sync(FULLM, v, 4, 8);
    v += __shfl_xor_sync(FULLM, v, 2, 8);
    v += __shfl_xor_sync(FULLM, v, 1, 8);
    return v;
}

// ============================================================
// K1: char-poly coeffs via Newton's identities (traces of powers)
// ============================================================
__global__ void __launch_bounds__(THREADS)
k1_fl(const float* __restrict__ Aall, float* __restrict__ out, int B)
{
    __shared__ double Msh[GPB][72];

    int tid = threadIdx.x, lane = tid & 7, grp = tid >> 3;
    int b = blockIdx.x * GPB + grp;
    int bb = (b < B) ? b : (B - 1);
    const float* Ap = Aall + (size_t)bb * 64;
    double* Mg = Msh[grp];

    float nrm2 = 0.f;
    #pragma unroll
    for (int i = 0; i < 64; i++) {
        float v = Ap[i];
        nrm2 = __fadd_rn(nrm2, __fmul_rn(v, v));
    }
    double scale = (double)sqrtf(nrm2) / 2.8284271247461903;
    scale = fmax(scale, 1e-12);
    double rscale = 1.0 / scale;

    double Asr[8];
    {
        const float4* Ap4 = (const float4*)(Ap + lane * 8);
        float4 q0 = Ap4[0], q1 = Ap4[1];
        Asr[0] = (double)q0.x * rscale; Asr[1] = (double)q0.y * rscale;
        Asr[2] = (double)q0.z * rscale; Asr[3] = (double)q0.w * rscale;
        Asr[4] = (double)q1.x * rscale; Asr[5] = (double)q1.y * rscale;
        Asr[6] = (double)q1.z * rscale; Asr[7] = (double)q1.w * rscale;
    }

    double dmine = 0.0;
    #pragma unroll
    for (int j = 0; j < 8; j++) if (lane == j) dmine = Asr[j];

    #pragma unroll
    for (int j = 0; j < 8; j++) Mg[lane * 9 + j] = Asr[j];
    __syncwarp();

    double p1 = dred(dmine);
    double s2 = 0.0;
    #pragma unroll
    for (int j = 0; j < 8; j++) s2 = fma(Asr[j], Asr[j], s2);
    double p2 = dred(s2);

    double A2r[8];
    #pragma unroll
    for (int j = 0; j < 8; j++) A2r[j] = 0.0;
    #pragma unroll
    for (int t = 0; t < 8; t++) {
        double w = Asr[t];
        #pragma unroll
        for (int j = 0; j < 8; j++) A2r[j] = fma(w, Mg[t * 9 + j], A2r[j]);
    }
    double s3 = 0.0, s4 = 0.0;
    #pragma unroll
    for (int j = 0; j < 8; j++) {
        s3 = fma(Asr[j], A2r[j], s3);
        s4 = fma(A2r[j], A2r[j], s4);
    }
    double p3 = dred(s3);
    double p4 = dred(s4);

    __syncwarp();
    #pragma unroll
    for (int j = 0; j < 8; j++) Mg[lane * 9 + j] = A2r[j];
    __syncwarp();

    double A3r[8];
    #pragma unroll
    for (int j = 0; j < 8; j++) A3r[j] = 0.0;
    #pragma unroll
    for (int t = 0; t < 8; t++) {
        double w = Asr[t];
        #pragma unroll
        for (int j = 0; j < 8; j++) A3r[j] = fma(w, Mg[t * 9 + j], A3r[j]);
    }
    double s5 = 0.0, s6 = 0.0;
    #pragma unroll
    for (int j = 0; j < 8; j++) {
        s5 = fma(A2r[j], A3r[j], s5);
        s6 = fma(A3r[j], A3r[j], s6);
    }
    double p5 = dred(s5);
    double p6 = dred(s6);

    __syncwarp();
    #pragma unroll
    for (int j = 0; j < 8; j++) Mg[lane * 9 + j] = A3r[j];
    __syncwarp();

    double A4r[8];
    #pragma unroll
    for (int j = 0; j < 8; j++) A4r[j] = 0.0;
    #pragma unroll
    for (int t = 0; t < 8; t++) {
        double w = Asr[t];
        #pragma unroll
        for (int j = 0; j < 8; j++) A4r[j] = fma(w, Mg[t * 9 + j], A4r[j]);
    }
    double s7 = 0.0, s8 = 0.0;
    #pragma unroll
    for (int j = 0; j < 8; j++) {
        s7 = fma(A3r[j], A4r[j], s7);
        s8 = fma(A4r[j], A4r[j], s8);
    }
    double p7 = dred(s7);
    double p8 = dred(s8);

    double e1 = p1;
    double e2 = (e1 * p1 - p2) / 2.0;
    double e3 = (e2 * p1 - e1 * p2 + p3) / 3.0;
    double e4 = (e3 * p1 - e2 * p2 + e1 * p3 - p4) / 4.0;
    double e5 = (e4 * p1 - e3 * p2 + e2 * p3 - e1 * p4 + p5) / 5.0;
    double e6 = (e5 * p1 - e4 * p2 + e3 * p3 - e2 * p4 + e1 * p5 - p6) / 6.0;
    double e7 = (e6 * p1 - e5 * p2 + e4 * p3 - e3 * p4 + e2 * p5 - e1 * p6 + p7) / 7.0;
    double e8 = (e7 * p1 - e6 * p2 + e5 * p3 - e4 * p4 + e3 * p5 - e2 * p6 + e1 * p7 - p8) / 8.0;

    double c[9];
    c[8] = 1.0;
    c[7] = -e1; c[6] = e2; c[5] = -e3; c[4] = e4;
    c[3] = -e5; c[2] = e6; c[1] = -e7; c[0] = e8;

    double zi[8];
    #pragma unroll
    for (int i = 0; i < 8; i++) zi[i] = dshfl(dmine, i);
    #pragma unroll 1
    for (int i = 1; i < 8; i++) {
        double key = zi[i];
        int j = i - 1;
        while (j >= 0 && zi[j] > key) { zi[j + 1] = zi[j]; j--; }
        zi[j + 1] = key;
    }

    if (b < B && lane == 0) {
        #pragma unroll
        for (int i = 0; i < 9; i++) g_c[(size_t)b * 9 + i] = c[i];
        #pragma unroll
        for (int i = 0; i < 8; i++) g_zi[(size_t)b * 8 + i] = zi[i];
        float* o_cc = out + (size_t)B * 72;
        #pragma unroll
        for (int i = 0; i < 8; i++) o_cc[(size_t)b * 8 + i] = (float)c[i];
    }
}

// ============================================================
// K2: Laguerre + deflation + polish (1 thread/batch, f64 FMA)
// ============================================================
__global__ void __launch_bounds__(128)
k2_lag(int B)
{
    int b = blockIdx.x * blockDim.x + threadIdx.x;
    if (b >= B) return;

    double c[9], cl[9], zi[8];
    #pragma unroll
    for (int i = 0; i < 9; i++) { c[i] = g_c[(size_t)b * 9 + i]; cl[i] = c[i]; }
    #pragma unroll
    for (int i = 0; i < 8; i++) zi[i] = g_zi[(size_t)b * 8 + i];

    const double lstep = 2e-4 / 7.0;
    double roots[8];
    float fric[8], sett[8];

    #pragma unroll
    for (int ri = 0; ri < 8; ri++) {
        const int deg = 8 - ri;
        const double dd = (double)deg;
        double z = zi[ri] + (-1e-4 + lstep * (double)ri);
        float fr = 0.f, st = (float)LAGI;
        #pragma unroll
        for (int it = 0; it < LAGI; it++) {
            double pv = cl[deg], dp = 0.0, d2 = 0.0;
            #pragma unroll
            for (int j = deg - 1; j >= 0; j--) {
                d2 = fma(d2, z, dp);
                dp = fma(dp, z, pv);
                pv = fma(pv, z, cl[j]);
            }
            float dp_abs = (float)fabs(dp);
            fr = __fadd_rn(fr, 1.0f / __fadd_rn(dp_abs, 1e-8f));
            float pv_abs = (float)fabs(pv);
            if (pv_abs < 1e-6f && st == (float)LAGI) st = (float)it;
            bool ok = fabs(pv) > 1e-30;
            double ps = ok ? pv : 1.0;
            double rps = 1.0 / ps;
            double G = ok ? (dp * rps) : 0.0;
            double GG = G * G;
            double twod2 = ok ? (2.0 * d2 * rps) : 0.0;
            double H = GG - twod2;
            double inner = fma(dd, H, -GG);
            double disc = (dd - 1.0) * inner;
            disc = disc > 0.0 ? disc : 0.0;
            double sq = sqrt(disc);
            double gp = G + sq, gm = G - sq;
            double den = (fabs(gp) >= fabs(gm)) ? gp : gm;
            bool dok = fabs(den) > 1e-20;
            double ds = dok ? den : 1.0;
            z = z - (dok ? (dd / ds) : 0.0);
        }
        roots[ri] = z; fric[ri] = fr; sett[ri] = st;
        double bcur = cl[deg];
        #pragma unroll
        for (int j = deg - 1; j >= 1; j--) {
            double tmp = cl[j];
            cl[j] = bcur;
            bcur = fma(z, bcur, tmp);
        }
        cl[0] = bcur;
    }

    #pragma unroll
    for (int p = 0; p < POLI; p++) {
        #pragma unroll
        for (int i = 0; i < 8; i++) {
            double r = roots[i];
            double pv = 1.0, dp = 0.0;
            #pragma unroll
            for (int j = 7; j >= 0; j--) {
                dp = fma(dp, r, pv);
                pv = fma(pv, r, c[j]);
            }
            if (fabs(dp) > 1e-30) r = r - pv / dp;
            roots[i] = r;
        }
    }

    #pragma unroll
    for (int i = 0; i < 8; i++) g_roots[(size_t)b * 8 + i] = roots[i];
    #pragma unroll
    for (int i = 0; i < 8; i++) {
        g_fs[(size_t)b * 16 + i]     = fric[i];
        g_fs[(size_t)b * 16 + 8 + i] = sett[i];
    }
}

// ============================================================
// K3: adjugate eigvecs via q(lam,A)=sum h_m A^m:
//     f32 powers for column selection, f64 Horner-in-A winning col,
//     then NS + outputs (verbatim R9 chain).
// ============================================================
__global__ void __launch_bounds__(THREADS)
k3_vec(const float* __restrict__ Aall, float* __restrict__ out, int B)
{
    __shared__ float Psh[GPB][7][72];   // A^1..A^7 in f32, 9-padded rows
    __shared__ float Fsh[GPB][72];

    int tid = threadIdx.x, lane = tid & 7, grp = tid >> 3;
    int b = blockIdx.x * GPB + grp;
    int bb = (b < B) ? b : (B - 1);
    const float* Ap = Aall + (size_t)bb * 64;
    float* Fg = Fsh[grp];

    float nrm2 = 0.f;
    #pragma unroll
    for (int i = 0; i < 64; i++) {
        float v = Ap[i];
        nrm2 = __fadd_rn(nrm2, __fmul_rn(v, v));
    }
    double scale = (double)sqrtf(nrm2) / 2.8284271247461903;
    scale = fmax(scale, 1e-12);
    double rscale = 1.0 / scale;

    double Asr[8];
    float Afs[8], Afr[8];
    {
        const float4* Ap4 = (const float4*)(Ap + lane * 8);
        float4 q0 = Ap4[0], q1 = Ap4[1];
        Afr[0] = q0.x; Afr[1] = q0.y; Afr[2] = q0.z; Afr[3] = q0.w;
        Afr[4] = q1.x; Afr[5] = q1.y; Afr[6] = q1.z; Afr[7] = q1.w;
        #pragma unroll
        for (int j = 0; j < 8; j++) {
            Asr[j] = (double)Afr[j] * rscale;
            Afs[j] = (float)Asr[j];
        }
    }

    // f32 powers A^1..A^7 in shared
    #pragma unroll
    for (int j = 0; j < 8; j++) Psh[grp][0][lane * 9 + j] = Afs[j];
    __syncwarp();
    #pragma unroll 1
    for (int mi = 1; mi < 7; mi++) {
        float s[8];
        #pragma unroll
        for (int j = 0; j < 8; j++) s[j] = 0.f;
        #pragma unroll
        for (int t = 0; t < 8; t++) {
            float w = Afs[t];
            #pragma unroll
            for (int j = 0; j < 8; j++)
                s[j] = fmaf(w, Psh[grp][mi - 1][t * 9 + j], s[j]);
        }
        __syncwarp();
        #pragma unroll
        for (int j = 0; j < 8; j++) Psh[grp][mi][lane * 9 + j] = s[j];
        __syncwarp();
    }

    // coefficients
    double cd[9];
    #pragma unroll
    for (int i = 0; i < 9; i++) cd[i] = g_c[(size_t)bb * 9 + i];
    float cf[9];
    #pragma unroll
    for (int i = 0; i < 9; i++) cf[i] = (float)cd[i];

    double rootmine = g_roots[(size_t)bb * 8 + lane];
    float frmine = g_fs[(size_t)bb * 16 + lane];
    float stmine = g_fs[(size_t)bb * 16 + 8 + lane];

    float Vrow[8];   // V[lane(component)][i]
    #pragma unroll 1
    for (int i = 0; i < 8; i++) {
        double lam = dshfl(rootmine, i);
        float lamf = (float)lam;

        // f32 h_m coefficients: h[m] = sum_u c[m+1+u] lam^u
        float h[8];
        {
            float t = 1.f;            // c[8]
            h[7] = t;
            #pragma unroll
            for (int m = 6; m >= 0; m--) {
                t = fmaf(t, lamf, cf[m + 1]);
                h[m] = t;
            }
        }
        // f32 column norm for column = lane
        float cn = 0.f;
        #pragma unroll
        for (int a = 0; a < 8; a++) {
            float r = (a == lane) ? h[0] : 0.f;
            #pragma unroll
            for (int mi = 0; mi < 7; mi++)
                r = fmaf(h[mi + 1], Psh[grp][mi][a * 9 + lane], r);
            cn = fmaf(r, r, cn);
        }
        // argmax over 8 lanes (first max wins)
        float bval = cn; int bidx = lane;
        #pragma unroll
        for (int off = 1; off < 8; off <<= 1) {
            float ov = __shfl_xor_sync(FULLM, bval, off, 8);
            int   oi = __shfl_xor_sync(FULLM, bidx, off, 8);
            if (ov > bval || (ov == bval && oi < bidx)) { bval = ov; bidx = oi; }
        }
        int best = bidx;

        // f64 h_m
        double hd[8];
        {
            double t = 1.0;
            hd[7] = t;
            #pragma unroll
            for (int m = 6; m >= 0; m--) {
                t = fma(t, lam, cd[m + 1]);
                hd[m] = t;
            }
        }
        // winning column: u = sum_m hd[m] A^m e_best via Horner-in-A
        double u = (lane == best) ? hd[7] : 0.0;
        #pragma unroll
        for (int m = 6; m >= 0; m--) {
            double un = (lane == best) ? hd[m] : 0.0;
            #pragma unroll
            for (int t = 0; t < 8; t++)
                un = fma(Asr[t], dshfl(u, t), un);
            u = un;
        }
        double s2 = dred(u * u);
        double nrm = sqrt(s2) + 1e-30;
        Vrow[i] = (float)(u / nrm);
    }

    // ---- stage V, NS orthogonalization (verbatim chain) ----
    #pragma unroll
    for (int j = 0; j < 8; j++) Fg[lane * 9 + j] = Vrow[j];
    __syncwarp();
    float Yrow[8], Xrow[8];
    #pragma unroll
    for (int j = 0; j < 8; j++) { Yrow[j] = 0.f; Xrow[j] = (lane == j) ? 1.f : 0.f; }
    #pragma unroll
    for (int a = 0; a < 8; a++) {
        float vai = Fg[a * 9 + lane];
        #pragma unroll
        for (int j = 0; j < 8; j++) Yrow[j] += vai * Fg[a * 9 + j];
    }

    #pragma unroll 1
    for (int ns = 0; ns < 2; ns++) {
        float Trow[8], Xn[8], Yn[8];
        #pragma unroll
        for (int j = 0; j < 8; j++) {
            Trow[j] = ((lane == j) ? 3.f : 0.f) - Yrow[j];
            Xn[j] = 0.f; Yn[j] = 0.f;
        }
        #pragma unroll
        for (int kk = 0; kk < 8; kk++) {
            float xk = Xrow[kk];
            float tk = Trow[kk];
            #pragma unroll
            for (int j = 0; j < 8; j++) {
                float tkj = fshfl(Trow[j], kk);
                float ykj = fshfl(Yrow[j], kk);
                Xn[j] += xk * tkj;
                Yn[j] += tk * ykj;
            }
        }
        #pragma unroll
        for (int j = 0; j < 8; j++) { Xrow[j] = 0.5f * Xn[j]; Yrow[j] = 0.5f * Yn[j]; }
    }
    {
        float Vn[8];
        #pragma unroll
        for (int j = 0; j < 8; j++) Vn[j] = 0.f;
        #pragma unroll
        for (int kk = 0; kk < 8; kk++) {
            float vk = Vrow[kk];
            #pragma unroll
            for (int j = 0; j < 8; j++) Vn[j] += vk * fshfl(Xrow[j], kk);
        }
        #pragma unroll
        for (int j = 0; j < 8; j++) Vrow[j] = Vn[j];
    }

    __syncwarp();
    #pragma unroll
    for (int j = 0; j < 8; j++) Fg[lane * 9 + j] = Vrow[j];
    __syncwarp();

    float rrp = 0.f;
    #pragma unroll
    for (int j = 0; j < 8; j++) {
        float s = 0.f;
        #pragma unroll
        for (int a = 0; a < 8; a++) s += Fg[a * 9 + lane] * Fg[a * 9 + j];
        float d = s - ((lane == j) ? 1.f : 0.f);
        rrp += d * d;
    }
    float rr = sqrtf(fred(rrp));

    float evals[8];
    #pragma unroll
    for (int i = 0; i < 8; i++) {
        float av = 0.f;
        #pragma unroll
        for (int k = 0; k < 8; k++) av += Afr[k] * Fg[k * 9 + i];
        evals[i] = fred(Vrow[i] * av);
    }

    int perm[8];
    #pragma unroll
    for (int i = 0; i < 8; i++) perm[i] = i;
    #pragma unroll 1
    for (int i = 1; i < 8; i++) {
        int key = perm[i];
        float kv = evals[key];
        int j = i - 1;
        while (j >= 0 && evals[perm[j]] > kv) { perm[j + 1] = perm[j]; j--; }
        perm[j + 1] = key;
    }

    if (b < B) {
        size_t Bs = (size_t)B;
        float* o_se = out;
        float* o_sv = out + Bs * 8;
        float* o_fr = out + Bs * 80;
        float* o_st = out + Bs * 88;
        float* o_eo = out + Bs * 96;
        float* o_rr = out + Bs * 104;

        int p = perm[lane];
        o_se[(size_t)b * 8 + lane] = evals[p];
        o_fr[(size_t)b * 8 + lane] = __shfl_sync(FULLM, frmine, p, 8);
        o_st[(size_t)b * 8 + lane] = __shfl_sync(FULLM, stmine, p, 8);
        o_eo[(size_t)b * 8 + lane] = (float)lane;
        if (lane == 0) o_rr[b] = rr;

        float outv[8];
        #pragma unroll
        for (int i = 0; i < 8; i++) {
            int pi = perm[i];
            float myv = Fg[lane * 9 + pi];
            float bvv = 0.f, sval = 0.f;
            #pragma unroll
            for (int a = 0; a < 8; a++) {
                float v = Fg[a * 9 + pi];
                float avv = fabsf(v);
                if (avv > bvv) { bvv = avv; sval = v; }
            }
            float sg = (sval > 0.f) ? 1.f : ((sval < 0.f) ? -1.f : 0.f);
            outv[i] = myv * sg;
        }
        float4* dst = (float4*)(o_sv + (size_t)b * 64 + lane * 8);
        dst[0] = make_float4(outv[0], outv[1], outv[2], outv[3]);
        dst[1] = make_float4(outv[4], outv[5], outv[6], outv[7]);
    }
}

extern "C" void kernel_launch(void* const* d_in, const int* in_sizes, int n_in,
                              void* d_out, int out_size)
{
    const float* A = (const float*)d_in[0];
    float* out = (float*)d_out;
    int B = in_sizes[0] / 64;
    int gblocks = (B + GPB - 1) / GPB;
    k1_fl<<<gblocks, THREADS>>>(A, out, B);
    k2_lag<<<(B + 127) / 128, 128>>>(B);
    k3_vec<<<gblocks, THREADS>>>(A, out, B);
}

// round 13
// speedup vs baseline: 1.9864x; 1.9864x over previous
#include <cuda_runtime.h>
#include <math.h>

#define LAGI 5
#define POLI 3
#define BMAX 65536
#define GPB 16
#define THREADS 128
#define FULLM 0xffffffffu

__device__ double g_c[BMAX * 9];
__device__ double g_zi[BMAX * 8];
__device__ double g_roots[BMAX * 8];
__device__ float  g_fs[BMAX * 16];
__device__ double g_P[(size_t)BMAX * 192];   // A2,A3,A4 rows: [b][p][i][j]

__device__ __forceinline__ double dshfl(double v, int s) {
    return __shfl_sync(FULLM, v, s, 8);
}
__device__ __forceinline__ double dred(double v) {
    v += __shfl_xor_sync(FULLM, v, 4, 8);
    v += __shfl_xor_sync(FULLM, v, 2, 8);
    v += __shfl_xor_sync(FULLM, v, 1, 8);
    return v;
}
__device__ __forceinline__ float fshfl(float v, int s) {
    return __shfl_sync(FULLM, v, s, 8);
}
__device__ __forceinline__ float fred(float v) {
    v += __shfl_xor_sync(FULLM, v, 4, 8);
    v += __shfl_xor_sync(FULLM, v, 2, 8);
    v += __shfl_xor_sync(FULLM, v, 1, 8);
    return v;
}

// fast f64 reciprocal: MUFU approx + 2 Newton steps (~1 ulp)
__device__ __forceinline__ double frcp64(double x) {
    double r;
    asm("rcp.approx.ftz.f64 %0, %1;" : "=d"(r) : "d"(x));
    double e = fma(-x, r, 1.0);
    r = fma(r, e, r);
    e = fma(-x, r, 1.0);
    r = fma(r, e, r);
    return r;
}
// fast f64 sqrt for x > 0 (normal): rsqrt approx + 2 NR, then x*y
__device__ __forceinline__ double fsqrt64(double x) {
    double y;
    asm("rsqrt.approx.ftz.f64 %0, %1;" : "=d"(y) : "d"(x));
    double h = 0.5 * x;
    double t = h * y * y;
    y = y * (1.5 - t);
    t = h * y * y;
    y = y * (1.5 - t);
    return x * y;
}

// ============================================================
// K1: Newton's identities char-poly; stores A2,A3,A4 for K3
// ============================================================
__global__ void __launch_bounds__(THREADS)
k1_fl(const float* __restrict__ Aall, float* __restrict__ out, int B)
{
    __shared__ double Msh[GPB][72];

    int tid = threadIdx.x, lane = tid & 7, grp = tid >> 3;
    int b = blockIdx.x * GPB + grp;
    int bb = (b < B) ? b : (B - 1);
    const float* Ap = Aall + (size_t)bb * 64;
    double* Mg = Msh[grp];

    float nrm2 = 0.f;
    #pragma unroll
    for (int i = 0; i < 64; i++) {
        float v = Ap[i];
        nrm2 = __fadd_rn(nrm2, __fmul_rn(v, v));
    }
    double scale = (double)sqrtf(nrm2) / 2.8284271247461903;
    scale = fmax(scale, 1e-12);
    double rscale = 1.0 / scale;

    double Asr[8];
    {
        const float4* Ap4 = (const float4*)(Ap + lane * 8);
        float4 q0 = Ap4[0], q1 = Ap4[1];
        Asr[0] = (double)q0.x * rscale; Asr[1] = (double)q0.y * rscale;
        Asr[2] = (double)q0.z * rscale; Asr[3] = (double)q0.w * rscale;
        Asr[4] = (double)q1.x * rscale; Asr[5] = (double)q1.y * rscale;
        Asr[6] = (double)q1.z * rscale; Asr[7] = (double)q1.w * rscale;
    }

    double dmine = 0.0;
    #pragma unroll
    for (int j = 0; j < 8; j++) if (lane == j) dmine = Asr[j];

    #pragma unroll
    for (int j = 0; j < 8; j++) Mg[lane * 9 + j] = Asr[j];
    __syncwarp();

    double p1 = dred(dmine);
    double s2 = 0.0;
    #pragma unroll
    for (int j = 0; j < 8; j++) s2 = fma(Asr[j], Asr[j], s2);
    double p2 = dred(s2);

    double A2r[8];
    #pragma unroll
    for (int j = 0; j < 8; j++) A2r[j] = 0.0;
    #pragma unroll
    for (int t = 0; t < 8; t++) {
        double w = Asr[t];
        #pragma unroll
        for (int j = 0; j < 8; j++) A2r[j] = fma(w, Mg[t * 9 + j], A2r[j]);
    }
    double s3 = 0.0, s4 = 0.0;
    #pragma unroll
    for (int j = 0; j < 8; j++) {
        s3 = fma(Asr[j], A2r[j], s3);
        s4 = fma(A2r[j], A2r[j], s4);
    }
    double p3 = dred(s3);
    double p4 = dred(s4);

    __syncwarp();
    #pragma unroll
    for (int j = 0; j < 8; j++) Mg[lane * 9 + j] = A2r[j];
    __syncwarp();

    double A3r[8];
    #pragma unroll
    for (int j = 0; j < 8; j++) A3r[j] = 0.0;
    #pragma unroll
    for (int t = 0; t < 8; t++) {
        double w = Asr[t];
        #pragma unroll
        for (int j = 0; j < 8; j++) A3r[j] = fma(w, Mg[t * 9 + j], A3r[j]);
    }
    double s5 = 0.0, s6 = 0.0;
    #pragma unroll
    for (int j = 0; j < 8; j++) {
        s5 = fma(A2r[j], A3r[j], s5);
        s6 = fma(A3r[j], A3r[j], s6);
    }
    double p5 = dred(s5);
    double p6 = dred(s6);

    __syncwarp();
    #pragma unroll
    for (int j = 0; j < 8; j++) Mg[lane * 9 + j] = A3r[j];
    __syncwarp();

    double A4r[8];
    #pragma unroll
    for (int j = 0; j < 8; j++) A4r[j] = 0.0;
    #pragma unroll
    for (int t = 0; t < 8; t++) {
        double w = Asr[t];
        #pragma unroll
        for (int j = 0; j < 8; j++) A4r[j] = fma(w, Mg[t * 9 + j], A4r[j]);
    }
    double s7 = 0.0, s8 = 0.0;
    #pragma unroll
    for (int j = 0; j < 8; j++) {
        s7 = fma(A3r[j], A4r[j], s7);
        s8 = fma(A4r[j], A4r[j], s8);
    }
    double p7 = dred(s7);
    double p8 = dred(s8);

    // store powers for K3
    if (b < B) {
        double* gp = g_P + (size_t)b * 192 + lane * 8;
        #pragma unroll
        for (int j = 0; j < 8; j++) gp[j]       = A2r[j];
        #pragma unroll
        for (int j = 0; j < 8; j++) gp[64 + j]  = A3r[j];
        #pragma unroll
        for (int j = 0; j < 8; j++) gp[128 + j] = A4r[j];
    }

    double e1 = p1;
    double e2 = (e1 * p1 - p2) * 0.5;
    double e3 = (e2 * p1 - e1 * p2 + p3) * (1.0 / 3.0);
    double e4 = (e3 * p1 - e2 * p2 + e1 * p3 - p4) * 0.25;
    double e5 = (e4 * p1 - e3 * p2 + e2 * p3 - e1 * p4 + p5) * 0.2;
    double e6 = (e5 * p1 - e4 * p2 + e3 * p3 - e2 * p4 + e1 * p5 - p6) * (1.0 / 6.0);
    double e7 = (e6 * p1 - e5 * p2 + e4 * p3 - e3 * p4 + e2 * p5 - e1 * p6 + p7) * (1.0 / 7.0);
    double e8 = (e7 * p1 - e6 * p2 + e5 * p3 - e4 * p4 + e3 * p5 - e2 * p6 + e1 * p7 - p8) * 0.125;

    double c[9];
    c[8] = 1.0;
    c[7] = -e1; c[6] = e2; c[5] = -e3; c[4] = e4;
    c[3] = -e5; c[2] = e6; c[1] = -e7; c[0] = e8;

    double zi[8];
    #pragma unroll
    for (int i = 0; i < 8; i++) zi[i] = dshfl(dmine, i);
    #pragma unroll 1
    for (int i = 1; i < 8; i++) {
        double key = zi[i];
        int j = i - 1;
        while (j >= 0 && zi[j] > key) { zi[j + 1] = zi[j]; j--; }
        zi[j + 1] = key;
    }

    if (b < B && lane == 0) {
        #pragma unroll
        for (int i = 0; i < 9; i++) g_c[(size_t)b * 9 + i] = c[i];
        #pragma unroll
        for (int i = 0; i < 8; i++) g_zi[(size_t)b * 8 + i] = zi[i];
        float* o_cc = out + (size_t)B * 72;
        #pragma unroll
        for (int i = 0; i < 8; i++) o_cc[(size_t)b * 8 + i] = (float)c[i];
    }
}

// ============================================================
// K2: Laguerre + deflation + polish (1 thread/batch, fast rcp/sqrt)
// ============================================================
__global__ void __launch_bounds__(128)
k2_lag(int B)
{
    int b = blockIdx.x * blockDim.x + threadIdx.x;
    if (b >= B) return;

    double c[9], cl[9], zi[8];
    #pragma unroll
    for (int i = 0; i < 9; i++) { c[i] = g_c[(size_t)b * 9 + i]; cl[i] = c[i]; }
    #pragma unroll
    for (int i = 0; i < 8; i++) zi[i] = g_zi[(size_t)b * 8 + i];

    const double lstep = 2e-4 / 7.0;
    double roots[8];
    float fric[8], sett[8];

    #pragma unroll
    for (int ri = 0; ri < 8; ri++) {
        const int deg = 8 - ri;
        const double dd = (double)deg;
        double z = zi[ri] + (-1e-4 + lstep * (double)ri);
        float fr = 0.f, st = (float)LAGI;
        #pragma unroll
        for (int it = 0; it < LAGI; it++) {
            double pv = cl[deg], dp = 0.0, d2 = 0.0;
            #pragma unroll
            for (int j = deg - 1; j >= 0; j--) {
                d2 = fma(d2, z, dp);
                dp = fma(dp, z, pv);
                pv = fma(pv, z, cl[j]);
            }
            float dp_abs = (float)fabs(dp);
            fr = __fadd_rn(fr, 1.0f / __fadd_rn(dp_abs, 1e-8f));
            float pv_abs = (float)fabs(pv);
            if (pv_abs < 1e-6f && st == (float)LAGI) st = (float)it;
            bool ok = fabs(pv) > 1e-30;
            double ps = ok ? pv : 1.0;
            double rps = frcp64(ps);
            double G = ok ? (dp * rps) : 0.0;
            double GG = G * G;
            double twod2 = ok ? (2.0 * d2 * rps) : 0.0;
            double H = GG - twod2;
            double inner = fma(dd, H, -GG);
            double disc = (dd - 1.0) * inner;
            double sq = 0.0;
            if (disc > 0.0) sq = fsqrt64(disc);
            double gp = G + sq, gm = G - sq;
            double den = (fabs(gp) >= fabs(gm)) ? gp : gm;
            bool dok = fabs(den) > 1e-20;
            double ds = dok ? den : 1.0;
            z = z - (dok ? (dd * frcp64(ds)) : 0.0);
        }
        roots[ri] = z; fric[ri] = fr; sett[ri] = st;
        double bcur = cl[deg];
        #pragma unroll
        for (int j = deg - 1; j >= 1; j--) {
            double tmp = cl[j];
            cl[j] = bcur;
            bcur = fma(z, bcur, tmp);
        }
        cl[0] = bcur;
    }

    #pragma unroll
    for (int p = 0; p < POLI; p++) {
        #pragma unroll
        for (int i = 0; i < 8; i++) {
            double r = roots[i];
            double pv = 1.0, dp = 0.0;
            #pragma unroll
            for (int j = 7; j >= 0; j--) {
                dp = fma(dp, r, pv);
                pv = fma(pv, r, c[j]);
            }
            if (fabs(dp) > 1e-30) r = r - pv * frcp64(dp);
            roots[i] = r;
        }
    }

    #pragma unroll
    for (int i = 0; i < 8; i++) g_roots[(size_t)b * 8 + i] = roots[i];
    #pragma unroll
    for (int i = 0; i < 8; i++) {
        g_fs[(size_t)b * 16 + i]     = fric[i];
        g_fs[(size_t)b * 16 + 8 + i] = sett[i];
    }
}

// ============================================================
// K3: adjugate eigvecs from stored powers (grouped Horner),
//     f32 selection, then NS + outputs.
// ============================================================
#define K3_PD_BYTES (GPB * 4 * 72 * 8)
#define K3_PF_BYTES (GPB * 7 * 72 * 4)
#define K3_FF_BYTES (GPB * 72 * 4)
#define K3_SMEM (K3_PD_BYTES + K3_PF_BYTES + K3_FF_BYTES)

__global__ void __launch_bounds__(THREADS)
k3_vec(const float* __restrict__ Aall, float* __restrict__ out, int B)
{
    extern __shared__ unsigned char sm3[];
    double* Pd = (double*)sm3;                                 // [GPB][4][72]
    float*  Pf = (float*)(sm3 + K3_PD_BYTES);                  // [GPB][7][72]
    float*  Ff = (float*)(sm3 + K3_PD_BYTES + K3_PF_BYTES);    // [GPB][72]

    int tid = threadIdx.x, lane = tid & 7, grp = tid >> 3;
    int b = blockIdx.x * GPB + grp;
    int bb = (b < B) ? b : (B - 1);
    const float* Ap = Aall + (size_t)bb * 64;
    double* Pdg = Pd + grp * 4 * 72;
    float*  Pfg = Pf + grp * 7 * 72;
    float*  Fg  = Ff + grp * 72;

    float nrm2 = 0.f;
    #pragma unroll
    for (int i = 0; i < 64; i++) {
        float v = Ap[i];
        nrm2 = __fadd_rn(nrm2, __fmul_rn(v, v));
    }
    double scale = (double)sqrtf(nrm2) / 2.8284271247461903;
    scale = fmax(scale, 1e-12);
    double rscale = 1.0 / scale;

    double Asr[8];
    float Afr[8], Afs[8];
    {
        const float4* Ap4 = (const float4*)(Ap + lane * 8);
        float4 q0 = Ap4[0], q1 = Ap4[1];
        Afr[0] = q0.x; Afr[1] = q0.y; Afr[2] = q0.z; Afr[3] = q0.w;
        Afr[4] = q1.x; Afr[5] = q1.y; Afr[6] = q1.z; Afr[7] = q1.w;
        #pragma unroll
        for (int j = 0; j < 8; j++) {
            Asr[j] = (double)Afr[j] * rscale;
            Afs[j] = (float)Asr[j];
        }
    }

    // stage f64 powers (A, A2, A3, A4) + f32 powers (A..A4)
    #pragma unroll
    for (int j = 0; j < 8; j++) {
        Pdg[0 * 72 + lane * 9 + j] = Asr[j];
        Pfg[0 * 72 + lane * 9 + j] = Afs[j];
    }
    {
        const double* gp = g_P + (size_t)bb * 192 + lane * 8;
        #pragma unroll
        for (int p = 0; p < 3; p++) {
            #pragma unroll
            for (int j = 0; j < 8; j++) {
                double v = gp[p * 64 + j];
                Pdg[(p + 1) * 72 + lane * 9 + j] = v;
                Pfg[(p + 1) * 72 + lane * 9 + j] = (float)v;
            }
        }
    }
    __syncwarp();

    // f32 A5, A6, A7 = A^p * A4 for p = 1..3
    #pragma unroll
    for (int pp = 0; pp < 3; pp++) {
        float s[8];
        #pragma unroll
        for (int j = 0; j < 8; j++) s[j] = 0.f;
        #pragma unroll
        for (int t = 0; t < 8; t++) {
            float w = Pfg[pp * 72 + lane * 9 + t];
            #pragma unroll
            for (int j = 0; j < 8; j++)
                s[j] = fmaf(w, Pfg[3 * 72 + t * 9 + j], s[j]);
        }
        #pragma unroll
        for (int j = 0; j < 8; j++) Pfg[(4 + pp) * 72 + lane * 9 + j] = s[j];
    }
    __syncwarp();

    double cd[9];
    #pragma unroll
    for (int i = 0; i < 9; i++) cd[i] = g_c[(size_t)bb * 9 + i];
    float cf[9];
    #pragma unroll
    for (int i = 0; i < 9; i++) cf[i] = (float)cd[i];

    double rootmine = g_roots[(size_t)bb * 8 + lane];
    float frmine = g_fs[(size_t)bb * 16 + lane];
    float stmine = g_fs[(size_t)bb * 16 + 8 + lane];

    float Vrow[8];   // V[lane(component)][i]
    #pragma unroll 1
    for (int i = 0; i < 8; i++) {
        double lam = dshfl(rootmine, i);
        float lamf = (float)lam;

        // f32 h coefficients
        float h[8];
        {
            float t = 1.f;
            h[7] = t;
            #pragma unroll
            for (int m = 6; m >= 0; m--) {
                t = fmaf(t, lamf, cf[m + 1]);
                h[m] = t;
            }
        }
        // f32 column norm for column = lane
        float cn = 0.f;
        #pragma unroll
        for (int a = 0; a < 8; a++) {
            float r = (a == lane) ? h[0] : 0.f;
            #pragma unroll
            for (int mi = 0; mi < 7; mi++)
                r = fmaf(h[mi + 1], Pfg[mi * 72 + a * 9 + lane], r);
            cn = fmaf(r, r, cn);
        }
        // argmax over lanes (first max wins)
        float bval = cn; int bidx = lane;
        #pragma unroll
        for (int off = 1; off < 8; off <<= 1) {
            float ov = __shfl_xor_sync(FULLM, bval, off, 8);
            int   oi = __shfl_xor_sync(FULLM, bidx, off, 8);
            if (ov > bval || (ov == bval && oi < bidx)) { bval = ov; bidx = oi; }
        }
        int best = bidx;

        // f64 h coefficients
        double hd[8];
        {
            double t = 1.0;
            hd[7] = t;
            #pragma unroll
            for (int m = 6; m >= 0; m--) {
                t = fma(t, lam, cd[m + 1]);
                hd[m] = t;
            }
        }
        // winning column: u = (h0 I + h1 A + h2 A2 + h3 A3)e + A4 (h4 I + h5 A + h6 A2 + h7 A3)e
        double idt = (lane == best) ? 1.0 : 0.0;
        double pA  = Pdg[0 * 72 + lane * 9 + best];
        double pA2 = Pdg[1 * 72 + lane * 9 + best];
        double pA3 = Pdg[2 * 72 + lane * 9 + best];
        double w1 = fma(hd[1], pA, hd[0] * idt);
        w1 = fma(hd[2], pA2, w1);
        w1 = fma(hd[3], pA3, w1);
        double w2 = fma(hd[5], pA, hd[4] * idt);
        w2 = fma(hd[6], pA2, w2);
        w2 = fma(hd[7], pA3, w2);
        double u = w1;
        #pragma unroll
        for (int t = 0; t < 8; t++)
            u = fma(Pdg[3 * 72 + lane * 9 + t], dshfl(w2, t), u);

        double s2 = dred(u * u);
        s2 = fmax(s2, 1e-60);
        double nrm = fsqrt64(s2) + 1e-30;
        Vrow[i] = (float)(u * frcp64(nrm));
    }

    // ---- NS orthogonalization + outputs (verbatim chain) ----
    #pragma unroll
    for (int j = 0; j < 8; j++) Fg[lane * 9 + j] = Vrow[j];
    __syncwarp();
    float Yrow[8], Xrow[8];
    #pragma unroll
    for (int j = 0; j < 8; j++) { Yrow[j] = 0.f; Xrow[j] = (lane == j) ? 1.f : 0.f; }
    #pragma unroll
    for (int a = 0; a < 8; a++) {
        float vai = Fg[a * 9 + lane];
        #pragma unroll
        for (int j = 0; j < 8; j++) Yrow[j] += vai * Fg[a * 9 + j];
    }

    #pragma unroll 1
    for (int ns = 0; ns < 2; ns++) {
        float Trow[8], Xn[8], Yn[8];
        #pragma unroll
        for (int j = 0; j < 8; j++) {
            Trow[j] = ((lane == j) ? 3.f : 0.f) - Yrow[j];
            Xn[j] = 0.f; Yn[j] = 0.f;
        }
        #pragma unroll
        for (int kk = 0; kk < 8; kk++) {
            float xk = Xrow[kk];
            float tk = Trow[kk];
            #pragma unroll
            for (int j = 0; j < 8; j++) {
                float tkj = fshfl(Trow[j], kk);
                float ykj = fshfl(Yrow[j], kk);
                Xn[j] += xk * tkj;
                Yn[j] += tk * ykj;
            }
        }
        #pragma unroll
        for (int j = 0; j < 8; j++) { Xrow[j] = 0.5f * Xn[j]; Yrow[j] = 0.5f * Yn[j]; }
    }
    {
        float Vn[8];
        #pragma unroll
        for (int j = 0; j < 8; j++) Vn[j] = 0.f;
        #pragma unroll
        for (int kk = 0; kk < 8; kk++) {
            float vk = Vrow[kk];
            #pragma unroll
            for (int j = 0; j < 8; j++) Vn[j] += vk * fshfl(Xrow[j], kk);
        }
        #pragma unroll
        for (int j = 0; j < 8; j++) Vrow[j] = Vn[j];
    }

    __syncwarp();
    #pragma unroll
    for (int j = 0; j < 8; j++) Fg[lane * 9 + j] = Vrow[j];
    __syncwarp();

    float rrp = 0.f;
    #pragma unroll
    for (int j = 0; j < 8; j++) {
        float s = 0.f;
        #pragma unroll
        for (int a = 0; a < 8; a++) s += Fg[a * 9 + lane] * Fg[a * 9 + j];
        float d = s - ((lane == j) ? 1.f : 0.f);
        rrp += d * d;
    }
    float rr = sqrtf(fred(rrp));

    float evals[8];
    #pragma unroll
    for (int i = 0; i < 8; i++) {
        float av = 0.f;
        #pragma unroll
        for (int k = 0; k < 8; k++) av += Afr[k] * Fg[k * 9 + i];
        evals[i] = fred(Vrow[i] * av);
    }

    int perm[8];
    #pragma unroll
    for (int i = 0; i < 8; i++) perm[i] = i;
    #pragma unroll 1
    for (int i = 1; i < 8; i++) {
        int key = perm[i];
        float kv = evals[key];
        int j = i - 1;
        while (j >= 0 && evals[perm[j]] > kv) { perm[j + 1] = perm[j]; j--; }
        perm[j + 1] = key;
    }

    if (b < B) {
        size_t Bs = (size_t)B;
        float* o_se = out;
        float* o_sv = out + Bs * 8;
        float* o_fr = out + Bs * 80;
        float* o_st = out + Bs * 88;
        float* o_eo = out + Bs * 96;
        float* o_rr = out + Bs * 104;

        int p = perm[lane];
        o_se[(size_t)b * 8 + lane] = evals[p];
        o_fr[(size_t)b * 8 + lane] = __shfl_sync(FULLM, frmine, p, 8);
        o_st[(size_t)b * 8 + lane] = __shfl_sync(FULLM, stmine, p, 8);
        o_eo[(size_t)b * 8 + lane] = (float)lane;
        if (lane == 0) o_rr[b] = rr;

        float outv[8];
        #pragma unroll
        for (int i = 0; i < 8; i++) {
            int pi = perm[i];
            float myv = Fg[lane * 9 + pi];
            float bvv = 0.f, sval = 0.f;
            #pragma unroll
            for (int a = 0; a < 8; a++) {
                float v = Fg[a * 9 + pi];
                float avv = fabsf(v);
                if (avv > bvv) { bvv = avv; sval = v; }
            }
            float sg = (sval > 0.f) ? 1.f : ((sval < 0.f) ? -1.f : 0.f);
            outv[i] = myv * sg;
        }
        float4* dst = (float4*)(o_sv + (size_t)b * 64 + lane * 8);
        dst[0] = make_float4(outv[0], outv[1], outv[2], outv[3]);
        dst[1] = make_float4(outv[4], outv[5], outv[6], outv[7]);
    }
}

extern "C" void kernel_launch(void* const* d_in, const int* in_sizes, int n_in,
                              void* d_out, int out_size)
{
    const float* A = (const float*)d_in[0];
    float* out = (float*)d_out;
    int B = in_sizes[0] / 64;
    int gblocks = (B + GPB - 1) / GPB;
    k1_fl<<<gblocks, THREADS>>>(A, out, B);
    k2_lag<<<(B + 127) / 128, 128>>>(B);
    cudaFuncSetAttribute(k3_vec, cudaFuncAttributeMaxDynamicSharedMemorySize, K3_SMEM);
    k3_vec<<<gblocks, THREADS, K3_SMEM>>>(A, out, B);
}

// round 15
// speedup vs baseline: 1.9922x; 1.0029x over previous
#include <cuda_runtime.h>
#include <math.h>

#define LAGI 5
#define POLI 3
#define BMAX 65536
#define GPB 16
#define THREADS 128
#define FULLM 0xffffffffu

__device__ double g_c[BMAX * 9];
__device__ double g_zi[BMAX * 8];
__device__ double g_roots[BMAX * 8];
__device__ float  g_fs[BMAX * 16];
__device__ double g_P[(size_t)BMAX * 192];   // A2,A3,A4 rows

__device__ __forceinline__ double dshfl(double v, int s) {
    return __shfl_sync(FULLM, v, s, 8);
}
__device__ __forceinline__ double dred(double v) {
    v += __shfl_xor_sync(FULLM, v, 4, 8);
    v += __shfl_xor_sync(FULLM, v, 2, 8);
    v += __shfl_xor_sync(FULLM, v, 1, 8);
    return v;
}
__device__ __forceinline__ float fshfl(float v, int s) {
    return __shfl_sync(FULLM, v, s, 8);
}
__device__ __forceinline__ float fred(float v) {
    v += __shfl_xor_sync(FULLM, v, 4, 8);
    v += __shfl_xor_sync(FULLM, v, 2, 8);
    v += __shfl_xor_sync(FULLM, v, 1, 8);
    return v;
}

__device__ __forceinline__ double frcp64(double x) {
    double r;
    asm("rcp.approx.ftz.f64 %0, %1;" : "=d"(r) : "d"(x));
    double e = fma(-x, r, 1.0);
    r = fma(r, e, r);
    e = fma(-x, r, 1.0);
    r = fma(r, e, r);
    return r;
}
__device__ __forceinline__ double fsqrt64(double x) {
    double y;
    asm("rsqrt.approx.ftz.f64 %0, %1;" : "=d"(y) : "d"(x));
    double h = 0.5 * x;
    double t = h * y * y;
    y = y * (1.5 - t);
    t = h * y * y;
    y = y * (1.5 - t);
    return x * y;
}

// ============================================================
// K1: Newton's identities char-poly; stores A2,A3,A4 for K3
// ============================================================
__global__ void __launch_bounds__(THREADS)
k1_fl(const float* __restrict__ Aall, float* __restrict__ out, int B)
{
    __shared__ double Msh[GPB][72];

    int tid = threadIdx.x, lane = tid & 7, grp = tid >> 3;
    int b = blockIdx.x * GPB + grp;
    int bb = (b < B) ? b : (B - 1);
    const float* Ap = Aall + (size_t)bb * 64;
    double* Mg = Msh[grp];

    float nrm2 = 0.f;
    #pragma unroll
    for (int i = 0; i < 64; i++) {
        float v = Ap[i];
        nrm2 = __fadd_rn(nrm2, __fmul_rn(v, v));
    }
    double scale = (double)sqrtf(nrm2) / 2.8284271247461903;
    scale = fmax(scale, 1e-12);
    double rscale = 1.0 / scale;

    double Asr[8];
    {
        const float4* Ap4 = (const float4*)(Ap + lane * 8);
        float4 q0 = Ap4[0], q1 = Ap4[1];
        Asr[0] = (double)q0.x * rscale; Asr[1] = (double)q0.y * rscale;
        Asr[2] = (double)q0.z * rscale; Asr[3] = (double)q0.w * rscale;
        Asr[4] = (double)q1.x * rscale; Asr[5] = (double)q1.y * rscale;
        Asr[6] = (double)q1.z * rscale; Asr[7] = (double)q1.w * rscale;
    }

    double dmine = 0.0;
    #pragma unroll
    for (int j = 0; j < 8; j++) if (lane == j) dmine = Asr[j];

    #pragma unroll
    for (int j = 0; j < 8; j++) Mg[lane * 9 + j] = Asr[j];
    __syncwarp();

    double p1 = dred(dmine);
    double s2 = 0.0;
    #pragma unroll
    for (int j = 0; j < 8; j++) s2 = fma(Asr[j], Asr[j], s2);
    double p2 = dred(s2);

    double A2r[8];
    #pragma unroll
    for (int j = 0; j < 8; j++) A2r[j] = 0.0;
    #pragma unroll
    for (int t = 0; t < 8; t++) {
        double w = Asr[t];
        #pragma unroll
        for (int j = 0; j < 8; j++) A2r[j] = fma(w, Mg[t * 9 + j], A2r[j]);
    }
    double s3 = 0.0, s4 = 0.0;
    #pragma unroll
    for (int j = 0; j < 8; j++) {
        s3 = fma(Asr[j], A2r[j], s3);
        s4 = fma(A2r[j], A2r[j], s4);
    }
    double p3 = dred(s3);
    double p4 = dred(s4);

    __syncwarp();
    #pragma unroll
    for (int j = 0; j < 8; j++) Mg[lane * 9 + j] = A2r[j];
    __syncwarp();

    double A3r[8];
    #pragma unroll
    for (int j = 0; j < 8; j++) A3r[j] = 0.0;
    #pragma unroll
    for (int t = 0; t < 8; t++) {
        double w = Asr[t];
        #pragma unroll
        for (int j = 0; j < 8; j++) A3r[j] = fma(w, Mg[t * 9 + j], A3r[j]);
    }
    double s5 = 0.0, s6 = 0.0;
    #pragma unroll
    for (int j = 0; j < 8; j++) {
        s5 = fma(A2r[j], A3r[j], s5);
        s6 = fma(A3r[j], A3r[j], s6);
    }
    double p5 = dred(s5);
    double p6 = dred(s6);

    __syncwarp();
    #pragma unroll
    for (int j = 0; j < 8; j++) Mg[lane * 9 + j] = A3r[j];
    __syncwarp();

    double A4r[8];
    #pragma unroll
    for (int j = 0; j < 8; j++) A4r[j] = 0.0;
    #pragma unroll
    for (int t = 0; t < 8; t++) {
        double w = Asr[t];
        #pragma unroll
        for (int j = 0; j < 8; j++) A4r[j] = fma(w, Mg[t * 9 + j], A4r[j]);
    }
    double s7 = 0.0, s8 = 0.0;
    #pragma unroll
    for (int j = 0; j < 8; j++) {
        s7 = fma(A3r[j], A4r[j], s7);
        s8 = fma(A4r[j], A4r[j], s8);
    }
    double p7 = dred(s7);
    double p8 = dred(s8);

    if (b < B) {
        double* gp = g_P + (size_t)b * 192 + lane * 8;
        #pragma unroll
        for (int j = 0; j < 8; j++) gp[j]       = A2r[j];
        #pragma unroll
        for (int j = 0; j < 8; j++) gp[64 + j]  = A3r[j];
        #pragma unroll
        for (int j = 0; j < 8; j++) gp[128 + j] = A4r[j];
    }

    double e1 = p1;
    double e2 = (e1 * p1 - p2) * 0.5;
    double e3 = (e2 * p1 - e1 * p2 + p3) * (1.0 / 3.0);
    double e4 = (e3 * p1 - e2 * p2 + e1 * p3 - p4) * 0.25;
    double e5 = (e4 * p1 - e3 * p2 + e2 * p3 - e1 * p4 + p5) * 0.2;
    double e6 = (e5 * p1 - e4 * p2 + e3 * p3 - e2 * p4 + e1 * p5 - p6) * (1.0 / 6.0);
    double e7 = (e6 * p1 - e5 * p2 + e4 * p3 - e3 * p4 + e2 * p5 - e1 * p6 + p7) * (1.0 / 7.0);
    double e8 = (e7 * p1 - e6 * p2 + e5 * p3 - e4 * p4 + e3 * p5 - e2 * p6 + e1 * p7 - p8) * 0.125;

    double c[9];
    c[8] = 1.0;
    c[7] = -e1; c[6] = e2; c[5] = -e3; c[4] = e4;
    c[3] = -e5; c[2] = e6; c[1] = -e7; c[0] = e8;

    double zi[8];
    #pragma unroll
    for (int i = 0; i < 8; i++) zi[i] = dshfl(dmine, i);
    #pragma unroll 1
    for (int i = 1; i < 8; i++) {
        double key = zi[i];
        int j = i - 1;
        while (j >= 0 && zi[j] > key) { zi[j + 1] = zi[j]; j--; }
        zi[j + 1] = key;
    }

    if (b < B && lane == 0) {
        #pragma unroll
        for (int i = 0; i < 9; i++) g_c[(size_t)b * 9 + i] = c[i];
        #pragma unroll
        for (int i = 0; i < 8; i++) g_zi[(size_t)b * 8 + i] = zi[i];
        float* o_cc = out + (size_t)B * 72;
        #pragma unroll
        for (int i = 0; i < 8; i++) o_cc[(size_t)b * 8 + i] = (float)c[i];
    }
}

// ============================================================
// K2: Laguerre + deflation + polish — TWO batches per thread,
//     interleaved for ILP (latency-bound chain).
// ============================================================
__global__ void __launch_bounds__(128)
k2_lag(int B)
{
    int idx = blockIdx.x * blockDim.x + threadIdx.x;
    int b0 = idx * 2;
    int b1 = idx * 2 + 1;
    if (b0 >= B) return;
    bool has1 = (b1 < B);
    int b1c = has1 ? b1 : b0;

    double c0[9], cl0[9], c1[9], cl1[9];
    #pragma unroll
    for (int i = 0; i < 9; i++) {
        c0[i] = g_c[(size_t)b0 * 9 + i]; cl0[i] = c0[i];
        c1[i] = g_c[(size_t)b1c * 9 + i]; cl1[i] = c1[i];
    }

    const double lstep = 2e-4 / 7.0;
    double roots0[8], roots1[8];

    #pragma unroll
    for (int ri = 0; ri < 8; ri++) {
        const int deg = 8 - ri;
        const double dd = (double)deg;
        double z0 = g_zi[(size_t)b0 * 8 + ri]  + (-1e-4 + lstep * (double)ri);
        double z1 = g_zi[(size_t)b1c * 8 + ri] + (-1e-4 + lstep * (double)ri);
        float fr0 = 0.f, st0 = (float)LAGI;
        float fr1 = 0.f, st1 = (float)LAGI;
        #pragma unroll
        for (int it = 0; it < LAGI; it++) {
            double pv0 = cl0[deg], dp0 = 0.0, d20 = 0.0;
            double pv1 = cl1[deg], dp1 = 0.0, d21 = 0.0;
            #pragma unroll
            for (int j = deg - 1; j >= 0; j--) {
                d20 = fma(d20, z0, dp0);
                d21 = fma(d21, z1, dp1);
                dp0 = fma(dp0, z0, pv0);
                dp1 = fma(dp1, z1, pv1);
                pv0 = fma(pv0, z0, cl0[j]);
                pv1 = fma(pv1, z1, cl1[j]);
            }
            float dpa0 = (float)fabs(dp0);
            float dpa1 = (float)fabs(dp1);
            fr0 = __fadd_rn(fr0, 1.0f / __fadd_rn(dpa0, 1e-8f));
            fr1 = __fadd_rn(fr1, 1.0f / __fadd_rn(dpa1, 1e-8f));
            float pva0 = (float)fabs(pv0);
            float pva1 = (float)fabs(pv1);
            if (pva0 < 1e-6f && st0 == (float)LAGI) st0 = (float)it;
            if (pva1 < 1e-6f && st1 == (float)LAGI) st1 = (float)it;
            bool ok0 = fabs(pv0) > 1e-30;
            bool ok1 = fabs(pv1) > 1e-30;
            double ps0 = ok0 ? pv0 : 1.0;
            double ps1 = ok1 ? pv1 : 1.0;
            double rps0 = frcp64(ps0);
            double rps1 = frcp64(ps1);
            double G0 = ok0 ? (dp0 * rps0) : 0.0;
            double G1 = ok1 ? (dp1 * rps1) : 0.0;
            double GG0 = G0 * G0;
            double GG1 = G1 * G1;
            double td0 = ok0 ? (2.0 * d20 * rps0) : 0.0;
            double td1 = ok1 ? (2.0 * d21 * rps1) : 0.0;
            double H0 = GG0 - td0;
            double H1 = GG1 - td1;
            double in0 = fma(dd, H0, -GG0);
            double in1 = fma(dd, H1, -GG1);
            double disc0 = (dd - 1.0) * in0;
            double disc1 = (dd - 1.0) * in1;
            double sq0 = 0.0, sq1 = 0.0;
            if (disc0 > 0.0) sq0 = fsqrt64(disc0);
            if (disc1 > 0.0) sq1 = fsqrt64(disc1);
            double gp0 = G0 + sq0, gm0 = G0 - sq0;
            double gp1 = G1 + sq1, gm1 = G1 - sq1;
            double den0 = (fabs(gp0) >= fabs(gm0)) ? gp0 : gm0;
            double den1 = (fabs(gp1) >= fabs(gm1)) ? gp1 : gm1;
            bool dok0 = fabs(den0) > 1e-20;
            bool dok1 = fabs(den1) > 1e-20;
            double ds0 = dok0 ? den0 : 1.0;
            double ds1 = dok1 ? den1 : 1.0;
            z0 = z0 - (dok0 ? (dd * frcp64(ds0)) : 0.0);
            z1 = z1 - (dok1 ? (dd * frcp64(ds1)) : 0.0);
        }
        roots0[ri] = z0; roots1[ri] = z1;
        g_fs[(size_t)b0 * 16 + ri] = fr0;
        g_fs[(size_t)b0 * 16 + 8 + ri] = st0;
        if (has1) {
            g_fs[(size_t)b1 * 16 + ri] = fr1;
            g_fs[(size_t)b1 * 16 + 8 + ri] = st1;
        }
        double bc0 = cl0[deg], bc1 = cl1[deg];
        #pragma unroll
        for (int j = deg - 1; j >= 1; j--) {
            double t0 = cl0[j], t1 = cl1[j];
            cl0[j] = bc0; cl1[j] = bc1;
            bc0 = fma(z0, bc0, t0);
            bc1 = fma(z1, bc1, t1);
        }
        cl0[0] = bc0; cl1[0] = bc1;
    }

    #pragma unroll
    for (int p = 0; p < POLI; p++) {
        #pragma unroll
        for (int i = 0; i < 8; i++) {
            double r0 = roots0[i], r1 = roots1[i];
            double pv0 = 1.0, dp0 = 0.0, pv1 = 1.0, dp1 = 0.0;
            #pragma unroll
            for (int j = 7; j >= 0; j--) {
                dp0 = fma(dp0, r0, pv0);
                dp1 = fma(dp1, r1, pv1);
                pv0 = fma(pv0, r0, c0[j]);
                pv1 = fma(pv1, r1, c1[j]);
            }
            if (fabs(dp0) > 1e-30) r0 = r0 - pv0 * frcp64(dp0);
            if (fabs(dp1) > 1e-30) r1 = r1 - pv1 * frcp64(dp1);
            roots0[i] = r0; roots1[i] = r1;
        }
    }

    #pragma unroll
    for (int i = 0; i < 8; i++) g_roots[(size_t)b0 * 8 + i] = roots0[i];
    if (has1) {
        #pragma unroll
        for (int i = 0; i < 8; i++) g_roots[(size_t)b1 * 8 + i] = roots1[i];
    }
}

// ============================================================
// K3: adjugate eigvecs from stored powers + NS + outputs
// ============================================================
#define K3_PD_BYTES (GPB * 4 * 72 * 8)
#define K3_PF_BYTES (GPB * 7 * 72 * 4)
#define K3_FF_BYTES (GPB * 72 * 4)
#define K3_SMEM (K3_PD_BYTES + K3_PF_BYTES + K3_FF_BYTES)

__global__ void __launch_bounds__(THREADS)
k3_vec(const float* __restrict__ Aall, float* __restrict__ out, int B)
{
    extern __shared__ unsigned char sm3[];
    double* Pd = (double*)sm3;
    float*  Pf = (float*)(sm3 + K3_PD_BYTES);
    float*  Ff = (float*)(sm3 + K3_PD_BYTES + K3_PF_BYTES);

    int tid = threadIdx.x, lane = tid & 7, grp = tid >> 3;
    int b = blockIdx.x * GPB + grp;
    int bb = (b < B) ? b : (B - 1);
    const float* Ap = Aall + (size_t)bb * 64;
    double* Pdg = Pd + grp * 4 * 72;
    float*  Pfg = Pf + grp * 7 * 72;
    float*  Fg  = Ff + grp * 72;

    float nrm2 = 0.f;
    #pragma unroll
    for (int i = 0; i < 64; i++) {
        float v = Ap[i];
        nrm2 = __fadd_rn(nrm2, __fmul_rn(v, v));
    }
    double scale = (double)sqrtf(nrm2) / 2.8284271247461903;
    scale = fmax(scale, 1e-12);
    double rscale = 1.0 / scale;

    double Asr[8];
    float Afr[8], Afs[8];
    {
        const float4* Ap4 = (const float4*)(Ap + lane * 8);
        float4 q0 = Ap4[0], q1 = Ap4[1];
        Afr[0] = q0.x; Afr[1] = q0.y; Afr[2] = q0.z; Afr[3] = q0.w;
        Afr[4] = q1.x; Afr[5] = q1.y; Afr[6] = q1.z; Afr[7] = q1.w;
        #pragma unroll
        for (int j = 0; j < 8; j++) {
            Asr[j] = (double)Afr[j] * rscale;
            Afs[j] = (float)Asr[j];
        }
    }

    #pragma unroll
    for (int j = 0; j < 8; j++) {
        Pdg[0 * 72 + lane * 9 + j] = Asr[j];
        Pfg[0 * 72 + lane * 9 + j] = Afs[j];
    }
    {
        const double* gp = g_P + (size_t)bb * 192 + lane * 8;
        #pragma unroll
        for (int p = 0; p < 3; p++) {
            #pragma unroll
            for (int j = 0; j < 8; j++) {
                double v = gp[p * 64 + j];
                Pdg[(p + 1) * 72 + lane * 9 + j] = v;
                Pfg[(p + 1) * 72 + lane * 9 + j] = (float)v;
            }
        }
    }
    __syncwarp();

    #pragma unroll
    for (int pp = 0; pp < 3; pp++) {
        float s[8];
        #pragma unroll
        for (int j = 0; j < 8; j++) s[j] = 0.f;
        #pragma unroll
        for (int t = 0; t < 8; t++) {
            float w = Pfg[pp * 72 + lane * 9 + t];
            #pragma unroll
            for (int j = 0; j < 8; j++)
                s[j] = fmaf(w, Pfg[3 * 72 + t * 9 + j], s[j]);
        }
        #pragma unroll
        for (int j = 0; j < 8; j++) Pfg[(4 + pp) * 72 + lane * 9 + j] = s[j];
    }
    __syncwarp();

    double cd[9];
    #pragma unroll
    for (int i = 0; i < 9; i++) cd[i] = g_c[(size_t)bb * 9 + i];
    float cf[9];
    #pragma unroll
    for (int i = 0; i < 9; i++) cf[i] = (float)cd[i];

    double rootmine = g_roots[(size_t)bb * 8 + lane];
    float frmine = g_fs[(size_t)bb * 16 + lane];
    float stmine = g_fs[(size_t)bb * 16 + 8 + lane];

    float Vrow[8];
    #pragma unroll 1
    for (int i = 0; i < 8; i++) {
        double lam = dshfl(rootmine, i);
        float lamf = (float)lam;

        float h[8];
        {
            float t = 1.f;
            h[7] = t;
            #pragma unroll
            for (int m = 6; m >= 0; m--) {
                t = fmaf(t, lamf, cf[m + 1]);
                h[m] = t;
            }
        }
        float cn = 0.f;
        #pragma unroll
        for (int a = 0; a < 8; a++) {
            float r = (a == lane) ? h[0] : 0.f;
            #pragma unroll
            for (int mi = 0; mi < 7; mi++)
                r = fmaf(h[mi + 1], Pfg[mi * 72 + a * 9 + lane], r);
            cn = fmaf(r, r, cn);
        }
        float bval = cn; int bidx = lane;
        #pragma unroll
        for (int off = 1; off < 8; off <<= 1) {
            float ov = __shfl_xor_sync(FULLM, bval, off, 8);
            int   oi = __shfl_xor_sync(FULLM, bidx, off, 8);
            if (ov > bval || (ov == bval && oi < bidx)) { bval = ov; bidx = oi; }
        }
        int best = bidx;

        double hd[8];
        {
            double t = 1.0;
            hd[7] = t;
            #pragma unroll
            for (int m = 6; m >= 0; m--) {
                t = fma(t, lam, cd[m + 1]);
                hd[m] = t;
            }
        }
        double idt = (lane == best) ? 1.0 : 0.0;
        double pA  = Pdg[0 * 72 + lane * 9 + best];
        double pA2 = Pdg[1 * 72 + lane * 9 + best];
        double pA3 = Pdg[2 * 72 + lane * 9 + best];
        double w1 = fma(hd[1], pA, hd[0] * idt);
        w1 = fma(hd[2], pA2, w1);
        w1 = fma(hd[3], pA3, w1);
        double w2 = fma(hd[5], pA, hd[4] * idt);
        w2 = fma(hd[6], pA2, w2);
        w2 = fma(hd[7], pA3, w2);
        double u = w1;
        #pragma unroll
        for (int t = 0; t < 8; t++)
            u = fma(Pdg[3 * 72 + lane * 9 + t], dshfl(w2, t), u);

        double s2 = dred(u * u);
        s2 = fmax(s2, 1e-60);
        double nrm = fsqrt64(s2) + 1e-30;
        Vrow[i] = (float)(u * frcp64(nrm));
    }

    #pragma unroll
    for (int j = 0; j < 8; j++) Fg[lane * 9 + j] = Vrow[j];
    __syncwarp();
    float Yrow[8], Xrow[8];
    #pragma unroll
    for (int j = 0; j < 8; j++) { Yrow[j] = 0.f; Xrow[j] = (lane == j) ? 1.f : 0.f; }
    #pragma unroll
    for (int a = 0; a < 8; a++) {
        float vai = Fg[a * 9 + lane];
        #pragma unroll
        for (int j = 0; j < 8; j++) Yrow[j] += vai * Fg[a * 9 + j];
    }

    #pragma unroll 1
    for (int ns = 0; ns < 2; ns++) {
        float Trow[8], Xn[8], Yn[8];
        #pragma unroll
        for (int j = 0; j < 8; j++) {
            Trow[j] = ((lane == j) ? 3.f : 0.f) - Yrow[j];
            Xn[j] = 0.f; Yn[j] = 0.f;
        }
        #pragma unroll
        for (int kk = 0; kk < 8; kk++) {
            float xk = Xrow[kk];
            float tk = Trow[kk];
            #pragma unroll
            for (int j = 0; j < 8; j++) {
                float tkj = fshfl(Trow[j], kk);
                float ykj = fshfl(Yrow[j], kk);
                Xn[j] += xk * tkj;
                Yn[j] += tk * ykj;
            }
        }
        #pragma unroll
        for (int j = 0; j < 8; j++) { Xrow[j] = 0.5f * Xn[j]; Yrow[j] = 0.5f * Yn[j]; }
    }
    {
        float Vn[8];
        #pragma unroll
        for (int j = 0; j < 8; j++) Vn[j] = 0.f;
        #pragma unroll
        for (int kk = 0; kk < 8; kk++) {
            float vk = Vrow[kk];
            #pragma unroll
            for (int j = 0; j < 8; j++) Vn[j] += vk * fshfl(Xrow[j], kk);
        }
        #pragma unroll
        for (int j = 0; j < 8; j++) Vrow[j] = Vn[j];
    }

    __syncwarp();
    #pragma unroll
    for (int j = 0; j < 8; j++) Fg[lane * 9 + j] = Vrow[j];
    __syncwarp();

    float rrp = 0.f;
    #pragma unroll
    for (int j = 0; j < 8; j++) {
        float s = 0.f;
        #pragma unroll
        for (int a = 0; a < 8; a++) s += Fg[a * 9 + lane] * Fg[a * 9 + j];
        float d = s - ((lane == j) ? 1.f : 0.f);
        rrp += d * d;
    }
    float rr = sqrtf(fred(rrp));

    float evals[8];
    #pragma unroll
    for (int i = 0; i < 8; i++) {
        float av = 0.f;
        #pragma unroll
        for (int k = 0; k < 8; k++) av += Afr[k] * Fg[k * 9 + i];
        evals[i] = fred(Vrow[i] * av);
    }

    int perm[8];
    #pragma unroll
    for (int i = 0; i < 8; i++) perm[i] = i;
    #pragma unroll 1
    for (int i = 1; i < 8; i++) {
        int key = perm[i];
        float kv = evals[key];
        int j = i - 1;
        while (j >= 0 && evals[perm[j]] > kv) { perm[j + 1] = perm[j]; j--; }
        perm[j + 1] = key;
    }

    if (b < B) {
        size_t Bs = (size_t)B;
        float* o_se = out;
        float* o_sv = out + Bs * 8;
        float* o_fr = out + Bs * 80;
        float* o_st = out + Bs * 88;
        float* o_eo = out + Bs * 96;
        float* o_rr = out + Bs * 104;

        int p = perm[lane];
        o_se[(size_t)b * 8 + lane] = evals[p];
        o_fr[(size_t)b * 8 + lane] = __shfl_sync(FULLM, frmine, p, 8);
        o_st[(size_t)b * 8 + lane] = __shfl_sync(FULLM, stmine, p, 8);
        o_eo[(size_t)b * 8 + lane] = (float)lane;
        if (lane == 0) o_rr[b] = rr;

        float outv[8];
        #pragma unroll
        for (int i = 0; i < 8; i++) {
            int pi = perm[i];
            float myv = Fg[lane * 9 + pi];
            float bvv = 0.f, sval = 0.f;
            #pragma unroll
            for (int a = 0; a < 8; a++) {
                float v = Fg[a * 9 + pi];
                float avv = fabsf(v);
                if (avv > bvv) { bvv = avv; sval = v; }
            }
            float sg = (sval > 0.f) ? 1.f : ((sval < 0.f) ? -1.f : 0.f);
            outv[i] = myv * sg;
        }
        float4* dst = (float4*)(o_sv + (size_t)b * 64 + lane * 8);
        dst[0] = make_float4(outv[0], outv[1], outv[2], outv[3]);
        dst[1] = make_float4(outv[4], outv[5], outv[6], outv[7]);
    }
}

extern "C" void kernel_launch(void* const* d_in, const int* in_sizes, int n_in,
                              void* d_out, int out_size)
{
    const float* A = (const float*)d_in[0];
    float* out = (float*)d_out;
    int B = in_sizes[0] / 64;
    int gblocks = (B + GPB - 1) / GPB;
    int k2threads = (B + 1) / 2;
    k1_fl<<<gblocks, THREADS>>>(A, out, B);
    k2_lag<<<(k2threads + 127) / 128, 128>>>(B);
    cudaFuncSetAttribute(k3_vec, cudaFuncAttributeMaxDynamicSharedMemorySize, K3_SMEM);
    k3_vec<<<gblocks, THREADS, K3_SMEM>>>(A, out, B);
}

// round 16
// speedup vs baseline: 2.2926x; 1.1508x over previous
#include <cuda_runtime.h>
#include <math.h>

#define LAGI 5
#define POLI 3
#define BMAX 65536
#define GPB 16
#define THREADS 128
#define FULLM 0xffffffffu

__device__ double g_c[BMAX * 9];
__device__ double g_zi[BMAX * 8];
__device__ double g_roots[BMAX * 8];
__device__ float  g_fs[BMAX * 16];
__device__ double g_P[(size_t)BMAX * 192];   // A2,A3,A4 rows

__device__ __forceinline__ double dshfl(double v, int s) {
    return __shfl_sync(FULLM, v, s, 8);
}
__device__ __forceinline__ double dred(double v) {
    v += __shfl_xor_sync(FULLM, v, 4, 8);
    v += __shfl_xor_sync(FULLM, v, 2, 8);
    v += __shfl_xor_sync(FULLM, v, 1, 8);
    return v;
}
__device__ __forceinline__ float fshfl(float v, int s) {
    return __shfl_sync(FULLM, v, s, 8);
}
__device__ __forceinline__ float fred(float v) {
    v += __shfl_xor_sync(FULLM, v, 4, 8);
    v += __shfl_xor_sync(FULLM, v, 2, 8);
    v += __shfl_xor_sync(FULLM, v, 1, 8);
    return v;
}

// fast f64 reciprocal: approx (err ~2^-28) + 1 Newton step -> full precision
__device__ __forceinline__ double frcp64(double x) {
    double r;
    asm("rcp.approx.ftz.f64 %0, %1;" : "=d"(r) : "d"(x));
    double e = fma(-x, r, 1.0);
    r = fma(r, e, r);
    return r;
}
// fast f64 sqrt for x > 0: rsqrt approx + 1 NR, then x*y
__device__ __forceinline__ double fsqrt64(double x) {
    double y;
    asm("rsqrt.approx.ftz.f64 %0, %1;" : "=d"(y) : "d"(x));
    double h = 0.5 * x;
    double t = h * y * y;
    y = y * (1.5 - t);
    return x * y;
}

// ============================================================
// K1: Newton's identities char-poly; stores A2,A3,A4 for K3
// ============================================================
__global__ void __launch_bounds__(THREADS)
k1_fl(const float* __restrict__ Aall, float* __restrict__ out, int B)
{
    __shared__ double Msh[GPB][72];

    int tid = threadIdx.x, lane = tid & 7, grp = tid >> 3;
    int b = blockIdx.x * GPB + grp;
    int bb = (b < B) ? b : (B - 1);
    const float* Ap = Aall + (size_t)bb * 64;
    double* Mg = Msh[grp];

    float nrm2 = 0.f;
    #pragma unroll
    for (int i = 0; i < 64; i++) {
        float v = Ap[i];
        nrm2 = __fadd_rn(nrm2, __fmul_rn(v, v));
    }
    double scale = (double)sqrtf(nrm2) / 2.8284271247461903;
    scale = fmax(scale, 1e-12);
    double rscale = 1.0 / scale;

    double Asr[8];
    {
        const float4* Ap4 = (const float4*)(Ap + lane * 8);
        float4 q0 = Ap4[0], q1 = Ap4[1];
        Asr[0] = (double)q0.x * rscale; Asr[1] = (double)q0.y * rscale;
        Asr[2] = (double)q0.z * rscale; Asr[3] = (double)q0.w * rscale;
        Asr[4] = (double)q1.x * rscale; Asr[5] = (double)q1.y * rscale;
        Asr[6] = (double)q1.z * rscale; Asr[7] = (double)q1.w * rscale;
    }

    double dmine = 0.0;
    #pragma unroll
    for (int j = 0; j < 8; j++) if (lane == j) dmine = Asr[j];

    #pragma unroll
    for (int j = 0; j < 8; j++) Mg[lane * 9 + j] = Asr[j];
    __syncwarp();

    double p1 = dred(dmine);
    double s2 = 0.0;
    #pragma unroll
    for (int j = 0; j < 8; j++) s2 = fma(Asr[j], Asr[j], s2);
    double p2 = dred(s2);

    double A2r[8];
    #pragma unroll
    for (int j = 0; j < 8; j++) A2r[j] = 0.0;
    #pragma unroll
    for (int t = 0; t < 8; t++) {
        double w = Asr[t];
        #pragma unroll
        for (int j = 0; j < 8; j++) A2r[j] = fma(w, Mg[t * 9 + j], A2r[j]);
    }
    double s3 = 0.0, s4 = 0.0;
    #pragma unroll
    for (int j = 0; j < 8; j++) {
        s3 = fma(Asr[j], A2r[j], s3);
        s4 = fma(A2r[j], A2r[j], s4);
    }
    double p3 = dred(s3);
    double p4 = dred(s4);

    __syncwarp();
    #pragma unroll
    for (int j = 0; j < 8; j++) Mg[lane * 9 + j] = A2r[j];
    __syncwarp();

    double A3r[8];
    #pragma unroll
    for (int j = 0; j < 8; j++) A3r[j] = 0.0;
    #pragma unroll
    for (int t = 0; t < 8; t++) {
        double w = Asr[t];
        #pragma unroll
        for (int j = 0; j < 8; j++) A3r[j] = fma(w, Mg[t * 9 + j], A3r[j]);
    }
    double s5 = 0.0, s6 = 0.0;
    #pragma unroll
    for (int j = 0; j < 8; j++) {
        s5 = fma(A2r[j], A3r[j], s5);
        s6 = fma(A3r[j], A3r[j], s6);
    }
    double p5 = dred(s5);
    double p6 = dred(s6);

    __syncwarp();
    #pragma unroll
    for (int j = 0; j < 8; j++) Mg[lane * 9 + j] = A3r[j];
    __syncwarp();

    double A4r[8];
    #pragma unroll
    for (int j = 0; j < 8; j++) A4r[j] = 0.0;
    #pragma unroll
    for (int t = 0; t < 8; t++) {
        double w = Asr[t];
        #pragma unroll
        for (int j = 0; j < 8; j++) A4r[j] = fma(w, Mg[t * 9 + j], A4r[j]);
    }
    double s7 = 0.0, s8 = 0.0;
    #pragma unroll
    for (int j = 0; j < 8; j++) {
        s7 = fma(A3r[j], A4r[j], s7);
        s8 = fma(A4r[j], A4r[j], s8);
    }
    double p7 = dred(s7);
    double p8 = dred(s8);

    if (b < B) {
        double* gp = g_P + (size_t)b * 192 + lane * 8;
        #pragma unroll
        for (int j = 0; j < 8; j++) gp[j]       = A2r[j];
        #pragma unroll
        for (int j = 0; j < 8; j++) gp[64 + j]  = A3r[j];
        #pragma unroll
        for (int j = 0; j < 8; j++) gp[128 + j] = A4r[j];
    }

    double e1 = p1;
    double e2 = (e1 * p1 - p2) * 0.5;
    double e3 = (e2 * p1 - e1 * p2 + p3) * (1.0 / 3.0);
    double e4 = (e3 * p1 - e2 * p2 + e1 * p3 - p4) * 0.25;
    double e5 = (e4 * p1 - e3 * p2 + e2 * p3 - e1 * p4 + p5) * 0.2;
    double e6 = (e5 * p1 - e4 * p2 + e3 * p3 - e2 * p4 + e1 * p5 - p6) * (1.0 / 6.0);
    double e7 = (e6 * p1 - e5 * p2 + e4 * p3 - e3 * p4 + e2 * p5 - e1 * p6 + p7) * (1.0 / 7.0);
    double e8 = (e7 * p1 - e6 * p2 + e5 * p3 - e4 * p4 + e3 * p5 - e2 * p6 + e1 * p7 - p8) * 0.125;

    double c[9];
    c[8] = 1.0;
    c[7] = -e1; c[6] = e2; c[5] = -e3; c[4] = e4;
    c[3] = -e5; c[2] = e6; c[1] = -e7; c[0] = e8;

    double zi[8];
    #pragma unroll
    for (int i = 0; i < 8; i++) zi[i] = dshfl(dmine, i);
    #pragma unroll 1
    for (int i = 1; i < 8; i++) {
        double key = zi[i];
        int j = i - 1;
        while (j >= 0 && zi[j] > key) { zi[j + 1] = zi[j]; j--; }
        zi[j + 1] = key;
    }

    if (b < B && lane == 0) {
        #pragma unroll
        for (int i = 0; i < 9; i++) g_c[(size_t)b * 9 + i] = c[i];
        #pragma unroll
        for (int i = 0; i < 8; i++) g_zi[(size_t)b * 8 + i] = zi[i];
        float* o_cc = out + (size_t)B * 72;
        #pragma unroll
        for (int i = 0; i < 8; i++) o_cc[(size_t)b * 8 + i] = (float)c[i];
    }
}

// ============================================================
// K2: Laguerre + deflation + polish — two batches/thread
// ============================================================
__global__ void __launch_bounds__(128)
k2_lag(int B)
{
    int idx = blockIdx.x * blockDim.x + threadIdx.x;
    int b0 = idx * 2;
    int b1 = idx * 2 + 1;
    if (b0 >= B) return;
    bool has1 = (b1 < B);
    int b1c = has1 ? b1 : b0;

    double c0[9], cl0[9], c1[9], cl1[9];
    #pragma unroll
    for (int i = 0; i < 9; i++) {
        c0[i] = g_c[(size_t)b0 * 9 + i]; cl0[i] = c0[i];
        c1[i] = g_c[(size_t)b1c * 9 + i]; cl1[i] = c1[i];
    }

    const double lstep = 2e-4 / 7.0;
    double roots0[8], roots1[8];

    #pragma unroll
    for (int ri = 0; ri < 8; ri++) {
        const int deg = 8 - ri;
        const double dd = (double)deg;
        double z0 = g_zi[(size_t)b0 * 8 + ri]  + (-1e-4 + lstep * (double)ri);
        double z1 = g_zi[(size_t)b1c * 8 + ri] + (-1e-4 + lstep * (double)ri);
        float fr0 = 0.f, st0 = (float)LAGI;
        float fr1 = 0.f, st1 = (float)LAGI;
        #pragma unroll
        for (int it = 0; it < LAGI; it++) {
            double pv0 = cl0[deg], dp0 = 0.0, d20 = 0.0;
            double pv1 = cl1[deg], dp1 = 0.0, d21 = 0.0;
            #pragma unroll
            for (int j = deg - 1; j >= 0; j--) {
                d20 = fma(d20, z0, dp0);
                d21 = fma(d21, z1, dp1);
                dp0 = fma(dp0, z0, pv0);
                dp1 = fma(dp1, z1, pv1);
                pv0 = fma(pv0, z0, cl0[j]);
                pv1 = fma(pv1, z1, cl1[j]);
            }
            float dpa0 = (float)fabs(dp0);
            float dpa1 = (float)fabs(dp1);
            fr0 = __fadd_rn(fr0, 1.0f / __fadd_rn(dpa0, 1e-8f));
            fr1 = __fadd_rn(fr1, 1.0f / __fadd_rn(dpa1, 1e-8f));
            float pva0 = (float)fabs(pv0);
            float pva1 = (float)fabs(pv1);
            if (pva0 < 1e-6f && st0 == (float)LAGI) st0 = (float)it;
            if (pva1 < 1e-6f && st1 == (float)LAGI) st1 = (float)it;
            bool ok0 = fabs(pv0) > 1e-30;
            bool ok1 = fabs(pv1) > 1e-30;
            double ps0 = ok0 ? pv0 : 1.0;
            double ps1 = ok1 ? pv1 : 1.0;
            double rps0 = frcp64(ps0);
            double rps1 = frcp64(ps1);
            double G0 = ok0 ? (dp0 * rps0) : 0.0;
            double G1 = ok1 ? (dp1 * rps1) : 0.0;
            double GG0 = G0 * G0;
            double GG1 = G1 * G1;
            double td0 = ok0 ? (2.0 * d20 * rps0) : 0.0;
            double td1 = ok1 ? (2.0 * d21 * rps1) : 0.0;
            double H0 = GG0 - td0;
            double H1 = GG1 - td1;
            double in0 = fma(dd, H0, -GG0);
            double in1 = fma(dd, H1, -GG1);
            double disc0 = (dd - 1.0) * in0;
            double disc1 = (dd - 1.0) * in1;
            double sq0 = 0.0, sq1 = 0.0;
            if (disc0 > 0.0) sq0 = fsqrt64(disc0);
            if (disc1 > 0.0) sq1 = fsqrt64(disc1);
            double gp0 = G0 + sq0, gm0 = G0 - sq0;
            double gp1 = G1 + sq1, gm1 = G1 - sq1;
            double den0 = (fabs(gp0) >= fabs(gm0)) ? gp0 : gm0;
            double den1 = (fabs(gp1) >= fabs(gm1)) ? gp1 : gm1;
            bool dok0 = fabs(den0) > 1e-20;
            bool dok1 = fabs(den1) > 1e-20;
            double ds0 = dok0 ? den0 : 1.0;
            double ds1 = dok1 ? den1 : 1.0;
            z0 = z0 - (dok0 ? (dd * frcp64(ds0)) : 0.0);
            z1 = z1 - (dok1 ? (dd * frcp64(ds1)) : 0.0);
        }
        roots0[ri] = z0; roots1[ri] = z1;
        g_fs[(size_t)b0 * 16 + ri] = fr0;
        g_fs[(size_t)b0 * 16 + 8 + ri] = st0;
        if (has1) {
            g_fs[(size_t)b1 * 16 + ri] = fr1;
            g_fs[(size_t)b1 * 16 + 8 + ri] = st1;
        }
        double bc0 = cl0[deg], bc1 = cl1[deg];
        #pragma unroll
        for (int j = deg - 1; j >= 1; j--) {
            double t0 = cl0[j], t1 = cl1[j];
            cl0[j] = bc0; cl1[j] = bc1;
            bc0 = fma(z0, bc0, t0);
            bc1 = fma(z1, bc1, t1);
        }
        cl0[0] = bc0; cl1[0] = bc1;
    }

    #pragma unroll
    for (int p = 0; p < POLI; p++) {
        #pragma unroll
        for (int i = 0; i < 8; i++) {
            double r0 = roots0[i], r1 = roots1[i];
            double pv0 = 1.0, dp0 = 0.0, pv1 = 1.0, dp1 = 0.0;
            #pragma unroll
            for (int j = 7; j >= 0; j--) {
                dp0 = fma(dp0, r0, pv0);
                dp1 = fma(dp1, r1, pv1);
                pv0 = fma(pv0, r0, c0[j]);
                pv1 = fma(pv1, r1, c1[j]);
            }
            if (fabs(dp0) > 1e-30) r0 = r0 - pv0 * frcp64(dp0);
            if (fabs(dp1) > 1e-30) r1 = r1 - pv1 * frcp64(dp1);
            roots0[i] = r0; roots1[i] = r1;
        }
    }

    #pragma unroll
    for (int i = 0; i < 8; i++) g_roots[(size_t)b0 * 8 + i] = roots0[i];
    if (has1) {
        #pragma unroll
        for (int i = 0; i < 8; i++) g_roots[(size_t)b1 * 8 + i] = roots1[i];
    }
}

// ============================================================
// K3: adjugate eigvecs from stored powers + NS + outputs
//     (f64 column value; f32 normalization)
// ============================================================
#define K3_PD_BYTES (GPB * 4 * 72 * 8)
#define K3_PF_BYTES (GPB * 7 * 72 * 4)
#define K3_FF_BYTES (GPB * 72 * 4)
#define K3_SMEM (K3_PD_BYTES + K3_PF_BYTES + K3_FF_BYTES)

__global__ void __launch_bounds__(THREADS)
k3_vec(const float* __restrict__ Aall, float* __restrict__ out, int B)
{
    extern __shared__ unsigned char sm3[];
    double* Pd = (double*)sm3;
    float*  Pf = (float*)(sm3 + K3_PD_BYTES);
    float*  Ff = (float*)(sm3 + K3_PD_BYTES + K3_PF_BYTES);

    int tid = threadIdx.x, lane = tid & 7, grp = tid >> 3;
    int b = blockIdx.x * GPB + grp;
    int bb = (b < B) ? b : (B - 1);
    const float* Ap = Aall + (size_t)bb * 64;
    double* Pdg = Pd + grp * 4 * 72;
    float*  Pfg = Pf + grp * 7 * 72;
    float*  Fg  = Ff + grp * 72;

    float nrm2 = 0.f;
    #pragma unroll
    for (int i = 0; i < 64; i++) {
        float v = Ap[i];
        nrm2 = __fadd_rn(nrm2, __fmul_rn(v, v));
    }
    double scale = (double)sqrtf(nrm2) / 2.8284271247461903;
    scale = fmax(scale, 1e-12);
    double rscale = 1.0 / scale;

    double Asr[8];
    float Afr[8], Afs[8];
    {
        const float4* Ap4 = (const float4*)(Ap + lane * 8);
        float4 q0 = Ap4[0], q1 = Ap4[1];
        Afr[0] = q0.x; Afr[1] = q0.y; Afr[2] = q0.z; Afr[3] = q0.w;
        Afr[4] = q1.x; Afr[5] = q1.y; Afr[6] = q1.z; Afr[7] = q1.w;
        #pragma unroll
        for (int j = 0; j < 8; j++) {
            Asr[j] = (double)Afr[j] * rscale;
            Afs[j] = (float)Asr[j];
        }
    }

    #pragma unroll
    for (int j = 0; j < 8; j++) {
        Pdg[0 * 72 + lane * 9 + j] = Asr[j];
        Pfg[0 * 72 + lane * 9 + j] = Afs[j];
    }
    {
        const double* gp = g_P + (size_t)bb * 192 + lane * 8;
        #pragma unroll
        for (int p = 0; p < 3; p++) {
            #pragma unroll
            for (int j = 0; j < 8; j++) {
                double v = gp[p * 64 + j];
                Pdg[(p + 1) * 72 + lane * 9 + j] = v;
                Pfg[(p + 1) * 72 + lane * 9 + j] = (float)v;
            }
        }
    }
    __syncwarp();

    #pragma unroll
    for (int pp = 0; pp < 3; pp++) {
        float s[8];
        #pragma unroll
        for (int j = 0; j < 8; j++) s[j] = 0.f;
        #pragma unroll
        for (int t = 0; t < 8; t++) {
            float w = Pfg[pp * 72 + lane * 9 + t];
            #pragma unroll
            for (int j = 0; j < 8; j++)
                s[j] = fmaf(w, Pfg[3 * 72 + t * 9 + j], s[j]);
        }
        #pragma unroll
        for (int j = 0; j < 8; j++) Pfg[(4 + pp) * 72 + lane * 9 + j] = s[j];
    }
    __syncwarp();

    double cd[9];
    #pragma unroll
    for (int i = 0; i < 9; i++) cd[i] = g_c[(size_t)bb * 9 + i];
    float cf[9];
    #pragma unroll
    for (int i = 0; i < 9; i++) cf[i] = (float)cd[i];

    double rootmine = g_roots[(size_t)bb * 8 + lane];
    float frmine = g_fs[(size_t)bb * 16 + lane];
    float stmine = g_fs[(size_t)bb * 16 + 8 + lane];

    float Vrow[8];
    #pragma unroll 1
    for (int i = 0; i < 8; i++) {
        double lam = dshfl(rootmine, i);
        float lamf = (float)lam;

        float h[8];
        {
            float t = 1.f;
            h[7] = t;
            #pragma unroll
            for (int m = 6; m >= 0; m--) {
                t = fmaf(t, lamf, cf[m + 1]);
                h[m] = t;
            }
        }
        float cn = 0.f;
        #pragma unroll
        for (int a = 0; a < 8; a++) {
            float r = (a == lane) ? h[0] : 0.f;
            #pragma unroll
            for (int mi = 0; mi < 7; mi++)
                r = fmaf(h[mi + 1], Pfg[mi * 72 + a * 9 + lane], r);
            cn = fmaf(r, r, cn);
        }
        float bval = cn; int bidx = lane;
        #pragma unroll
        for (int off = 1; off < 8; off <<= 1) {
            float ov = __shfl_xor_sync(FULLM, bval, off, 8);
            int   oi = __shfl_xor_sync(FULLM, bidx, off, 8);
            if (ov > bval || (ov == bval && oi < bidx)) { bval = ov; bidx = oi; }
        }
        int best = bidx;

        double hd[8];
        {
            double t = 1.0;
            hd[7] = t;
            #pragma unroll
            for (int m = 6; m >= 0; m--) {
                t = fma(t, lam, cd[m + 1]);
                hd[m] = t;
            }
        }
        double idt = (lane == best) ? 1.0 : 0.0;
        double pA  = Pdg[0 * 72 + lane * 9 + best];
        double pA2 = Pdg[1 * 72 + lane * 9 + best];
        double pA3 = Pdg[2 * 72 + lane * 9 + best];
        double w1 = fma(hd[1], pA, hd[0] * idt);
        w1 = fma(hd[2], pA2, w1);
        w1 = fma(hd[3], pA3, w1);
        double w2 = fma(hd[5], pA, hd[4] * idt);
        w2 = fma(hd[6], pA2, w2);
        w2 = fma(hd[7], pA3, w2);
        double u = w1;
        #pragma unroll
        for (int t = 0; t < 8; t++)
            u = fma(Pdg[3 * 72 + lane * 9 + t], dshfl(w2, t), u);

        // f64-accurate norm^2, f32 sqrt + divide
        double s2 = dred(u * u);
        float s2f = fmaxf((float)s2, 1e-38f);
        float nrmf = sqrtf(s2f) + 1e-30f;
        Vrow[i] = (float)u / nrmf;
    }

    #pragma unroll
    for (int j = 0; j < 8; j++) Fg[lane * 9 + j] = Vrow[j];
    __syncwarp();
    float Yrow[8], Xrow[8];
    #pragma unroll
    for (int j = 0; j < 8; j++) { Yrow[j] = 0.f; Xrow[j] = (lane == j) ? 1.f : 0.f; }
    #pragma unroll
    for (int a = 0; a < 8; a++) {
        float vai = Fg[a * 9 + lane];
        #pragma unroll
        for (int j = 0; j < 8; j++) Yrow[j] += vai * Fg[a * 9 + j];
    }

    #pragma unroll 1
    for (int ns = 0; ns < 2; ns++) {
        float Trow[8], Xn[8], Yn[8];
        #pragma unroll
        for (int j = 0; j < 8; j++) {
            Trow[j] = ((lane == j) ? 3.f : 0.f) - Yrow[j];
            Xn[j] = 0.f; Yn[j] = 0.f;
        }
        #pragma unroll
        for (int kk = 0; kk < 8; kk++) {
            float xk = Xrow[kk];
            float tk = Trow[kk];
            #pragma unroll
            for (int j = 0; j < 8; j++) {
                float tkj = fshfl(Trow[j], kk);
                float ykj = fshfl(Yrow[j], kk);
                Xn[j] += xk * tkj;
                Yn[j] += tk * ykj;
            }
        }
        #pragma unroll
        for (int j = 0; j < 8; j++) { Xrow[j] = 0.5f * Xn[j]; Yrow[j] = 0.5f * Yn[j]; }
    }
    {
        float Vn[8];
        #pragma unroll
        for (int j = 0; j < 8; j++) Vn[j] = 0.f;
        #pragma unroll
        for (int kk = 0; kk < 8; kk++) {
            float vk = Vrow[kk];
            #pragma unroll
            for (int j = 0; j < 8; j++) Vn[j] += vk * fshfl(Xrow[j], kk);
        }
        #pragma unroll
        for (int j = 0; j < 8; j++) Vrow[j] = Vn[j];
    }

    __syncwarp();
    #pragma unroll
    for (int j = 0; j < 8; j++) Fg[lane * 9 + j] = Vrow[j];
    __syncwarp();

    float rrp = 0.f;
    #pragma unroll
    for (int j = 0; j < 8; j++) {
        float s = 0.f;
        #pragma unroll
        for (int a = 0; a < 8; a++) s += Fg[a * 9 + lane] * Fg[a * 9 + j];
        float d = s - ((lane == j) ? 1.f : 0.f);
        rrp += d * d;
    }
    float rr = sqrtf(fred(rrp));

    float evals[8];
    #pragma unroll
    for (int i = 0; i < 8; i++) {
        float av = 0.f;
        #pragma unroll
        for (int k = 0; k < 8; k++) av += Afr[k] * Fg[k * 9 + i];
        evals[i] = fred(Vrow[i] * av);
    }

    int perm[8];
    #pragma unroll
    for (int i = 0; i < 8; i++) perm[i] = i;
    #pragma unroll 1
    for (int i = 1; i < 8; i++) {
        int key = perm[i];
        float kv = evals[key];
        int j = i - 1;
        while (j >= 0 && evals[perm[j]] > kv) { perm[j + 1] = perm[j]; j--; }
        perm[j + 1] = key;
    }

    if (b < B) {
        size_t Bs = (size_t)B;
        float* o_se = out;
        float* o_sv = out + Bs * 8;
        float* o_fr = out + Bs * 80;
        float* o_st = out + Bs * 88;
        float* o_eo = out + Bs * 96;
        float* o_rr = out + Bs * 104;

        int p = perm[lane];
        o_se[(size_t)b * 8 + lane] = evals[p];
        o_fr[(size_t)b * 8 + lane] = __shfl_sync(FULLM, frmine, p, 8);
        o_st[(size_t)b * 8 + lane] = __shfl_sync(FULLM, stmine, p, 8);
        o_eo[(size_t)b * 8 + lane] = (float)lane;
        if (lane == 0) o_rr[b] = rr;

        float outv[8];
        #pragma unroll
        for (int i = 0; i < 8; i++) {
            int pi = perm[i];
            float myv = Fg[lane * 9 + pi];
            float bvv = 0.f, sval = 0.f;
            #pragma unroll
            for (int a = 0; a < 8; a++) {
                float v = Fg[a * 9 + pi];
                float avv = fabsf(v);
                if (avv > bvv) { bvv = avv; sval = v; }
            }
            float sg = (sval > 0.f) ? 1.f : ((sval < 0.f) ? -1.f : 0.f);
            outv[i] = myv * sg;
        }
        float4* dst = (float4*)(o_sv + (size_t)b * 64 + lane * 8);
        dst[0] = make_float4(outv[0], outv[1], outv[2], outv[3]);
        dst[1] = make_float4(outv[4], outv[5], outv[6], outv[7]);
    }
}

extern "C" void kernel_launch(void* const* d_in, const int* in_sizes, int n_in,
                              void* d_out, int out_size)
{
    const float* A = (const float*)d_in[0];
    float* out = (float*)d_out;
    int B = in_sizes[0] / 64;
    int gblocks = (B + GPB - 1) / GPB;
    int k2threads = (B + 1) / 2;
    k1_fl<<<gblocks, THREADS>>>(A, out, B);
    k2_lag<<<(k2threads + 127) / 128, 128>>>(B);
    cudaFuncSetAttribute(k3_vec, cudaFuncAttributeMaxDynamicSharedMemorySize, K3_SMEM);
    k3_vec<<<gblocks, THREADS, K3_SMEM>>>(A, out, B);
}